// round 3
// baseline (speedup 1.0000x reference)
#include <cuda_runtime.h>
#include <cstdint>
#include <cstddef>

#define H 256
#define NHEADS 6
#define SEQ 4096
#define G3H 768
#define CLUSTER_N 8

// ================= helpers =================
__device__ __forceinline__ uint32_t smem_to_u32(const void* smem_ptr) {
    uint32_t addr;
    asm("{ .reg .u64 tmp; cvta.to.shared.u64 tmp, %1; cvt.u32.u64 %0, tmp; }"
        : "=r"(addr) : "l"(smem_ptr));
    return addr;
}
__device__ __forceinline__ uint32_t f2tf(float v) {
    uint32_t o;
    asm("cvt.rna.tf32.f32 %0, %1;" : "=r"(o) : "f"(v));
    return o;
}
#define MBARRIER_INIT(mbar, count) \
    asm volatile("mbarrier.init.shared.b64 [%0], %1;" \
                 :: "r"((uint32_t)(mbar)), "r"((uint32_t)(count)) : "memory")
#define MBAR_ARRIVE_REL_CLUSTER(addr) \
    asm volatile("mbarrier.arrive.release.cluster.shared::cluster.b64 _, [%0];" \
                 :: "r"(addr) : "memory")
#define MBAR_WAIT_PARITY_CLUSTER(mbar, parity) do { \
    uint32_t _m = (mbar), _p = (parity), _d; \
    asm volatile("{\n\t.reg .pred p;\n\t" \
        "mbarrier.try_wait.parity.acquire.cluster.shared::cta.b64 p, [%1], %2;\n\t" \
        "selp.b32 %0,1,0,p;\n\t}" : "=r"(_d) : "r"(_m), "r"(_p) : "memory"); \
    if (!_d) { \
        asm volatile("{\n\t.reg .pred P1;\n\t" \
            "WLC_%=:\n\t" \
            "mbarrier.try_wait.parity.acquire.cluster.shared::cta.b64 P1, [%0], %1, 0x989680;\n\t" \
            "@P1 bra.uni WDC_%=;\n\t" \
            "bra.uni WLC_%=;\n\t" \
            "WDC_%=:\n\t}" :: "r"(_m), "r"(_p) : "memory"); \
    } \
} while (0)

#define MMA_TF32(d, a, b) \
    asm volatile("mma.sync.aligned.m16n8k8.row.col.f32.tf32.tf32.f32 " \
        "{%0,%1,%2,%3}, {%4,%5,%6,%7}, {%8,%9}, {%0,%1,%2,%3};" \
        : "+f"((d)[0]), "+f"((d)[1]), "+f"((d)[2]), "+f"((d)[3]) \
        : "r"((a)[0]), "r"((a)[1]), "r"((a)[2]), "r"((a)[3]), \
          "r"((b)[0]), "r"((b)[1]))

// ---------------- device scratch ----------------
__device__ float g_x[SEQ * H];
__device__ float g_q[NHEADS * SEQ * H];
__device__ float g_k[NHEADS * SEQ * H];
__device__ float g_v[NHEADS * SEQ * H];
__device__ float g_vt[NHEADS * H * SEQ];
__device__ float g_scores[(size_t)NHEADS * SEQ * SEQ];   // 402 MB
__device__ float g_oc[SEQ * NHEADS * H];
__device__ float g_y0[SEQ * H];
__device__ float g_y[SEQ * H];
__device__ float g_gi[SEQ * G3H];
__device__ float g_hT[H];
__device__ float g_wqt[NHEADS * H * H];
__device__ float g_wkt[NHEADS * H * H];
__device__ float g_wvt[NHEADS * H * H];
__device__ float g_wot[H * NHEADS * H];

// ---------------- embedding gather ----------------
__global__ void embed_kernel(const int* __restrict__ tok,
                             const float* __restrict__ emb,
                             float* __restrict__ x) {
    int s = blockIdx.x, d = threadIdx.x;
    x[s * H + d] = emb[(size_t)tok[s] * H + d];
}

// ---------------- generic batched transpose: out[C][R] = in[R][C] ----------------
__global__ __launch_bounds__(256)
void transpose_k(const float* __restrict__ in, float* __restrict__ out,
                 int R, int C, long long sI, long long sO) {
    __shared__ float tile[32][33];
    in += (long long)blockIdx.z * sI;
    out += (long long)blockIdx.z * sO;
    int r0 = blockIdx.y * 32, c0 = blockIdx.x * 32;
    int tx = threadIdx.x & 31, ty = threadIdx.x >> 5;
#pragma unroll
    for (int i = 0; i < 32; i += 8)
        tile[ty + i][tx] = in[(size_t)(r0 + ty + i) * C + c0 + tx];
    __syncthreads();
#pragma unroll
    for (int i = 0; i < 32; i += 8)
        out[(size_t)(c0 + ty + i) * R + r0 + tx] = tile[tx][ty + i];
}

// ================= tf32 mma.sync GEMM: C = alpha*(A @ B^T) (+bias) =================
// A: [M,K] lda, B: [N,K] ldb, fp32. CTA tile 128x128, K-tile 32, 8 warps (4x2),
// warp tile 32x64 = 2x8 m16n8k8 atoms. SMEM row stride 36 floats (conflict-free).
#define SMEM_MMA (4 * 128 * 36 * 4)   // 73728 B

template <bool HASBIAS>
__global__ __launch_bounds__(256)
void mma_nt(const float* __restrict__ A, const float* __restrict__ B,
            const float* __restrict__ bias, float* __restrict__ C,
            int K, int lda, int ldb, int ldc,
            long long sA, long long sB, long long sBias, long long sC,
            float alpha) {
    extern __shared__ float sm[];
    float* Abuf[2] = {sm, sm + 128 * 36};
    float* Bbuf[2] = {sm + 2 * 128 * 36, sm + 3 * 128 * 36};
    const int bz = blockIdx.z;
    A += (long long)bz * sA;
    B += (long long)bz * sB;
    C += (long long)bz * sC;
    const float* bi = nullptr;
    if (HASBIAS) bi = bias + (long long)bz * sBias;
    const int bm = blockIdx.y * 128, bn = blockIdx.x * 128;
    const int tid = threadIdx.x, lane = tid & 31, wid = tid >> 5;
    const int wm = (wid & 3) * 32, wn = (wid >> 2) * 64;

    float acc[2][8][4];
#pragma unroll
    for (int i = 0; i < 2; i++)
#pragma unroll
        for (int j = 0; j < 8; j++)
#pragma unroll
            for (int q = 0; q < 4; q++) acc[i][j][q] = 0.f;

    float4 la[4], lb[4];
    // prologue: stage k-tile 0 into buffer 0
    {
#pragma unroll
        for (int j = 0; j < 4; j++) {
            int idx = tid + 256 * j;
            int r = idx >> 3, c = idx & 7;
            la[j] = *(const float4*)(A + (size_t)(bm + r) * lda + c * 4);
            lb[j] = *(const float4*)(B + (size_t)(bn + r) * ldb + c * 4);
        }
#pragma unroll
        for (int j = 0; j < 4; j++) {
            int idx = tid + 256 * j;
            int r = idx >> 3, c = idx & 7;
            *(float4*)&Abuf[0][r * 36 + c * 4] = make_float4(
                __uint_as_float(f2tf(la[j].x)), __uint_as_float(f2tf(la[j].y)),
                __uint_as_float(f2tf(la[j].z)), __uint_as_float(f2tf(la[j].w)));
            *(float4*)&Bbuf[0][r * 36 + c * 4] = make_float4(
                __uint_as_float(f2tf(lb[j].x)), __uint_as_float(f2tf(lb[j].y)),
                __uint_as_float(f2tf(lb[j].z)), __uint_as_float(f2tf(lb[j].w)));
        }
        __syncthreads();
    }

    const int nkt = K >> 5;
    for (int kt = 0; kt < nkt; kt++) {
        const int cur = kt & 1;
        if (kt + 1 < nkt) {
            const int k0 = (kt + 1) * 32;
#pragma unroll
            for (int j = 0; j < 4; j++) {
                int idx = tid + 256 * j;
                int r = idx >> 3, c = idx & 7;
                la[j] = *(const float4*)(A + (size_t)(bm + r) * lda + k0 + c * 4);
                lb[j] = *(const float4*)(B + (size_t)(bn + r) * ldb + k0 + c * 4);
            }
        }
        const float* Ab = Abuf[cur];
        const float* Bb = Bbuf[cur];
        const int r0 = wm + (lane >> 2), qq = lane & 3;
#pragma unroll
        for (int ks = 0; ks < 4; ks++) {
            const int k0 = ks * 8 + qq;
            uint32_t af[2][4];
#pragma unroll
            for (int am = 0; am < 2; am++) {
                int rb = (r0 + am * 16) * 36;
                af[am][0] = __float_as_uint(Ab[rb + k0]);
                af[am][1] = __float_as_uint(Ab[rb + 8 * 36 + k0]);
                af[am][2] = __float_as_uint(Ab[rb + k0 + 4]);
                af[am][3] = __float_as_uint(Ab[rb + 8 * 36 + k0 + 4]);
            }
#pragma unroll
            for (int bb = 0; bb < 8; bb++) {
                int nb = (wn + bb * 8 + (lane >> 2)) * 36;
                uint32_t bf[2] = {__float_as_uint(Bb[nb + k0]),
                                  __float_as_uint(Bb[nb + k0 + 4])};
                MMA_TF32(acc[0][bb], af[0], bf);
                MMA_TF32(acc[1][bb], af[1], bf);
            }
        }
        if (kt + 1 < nkt) {
            const int nb = (kt + 1) & 1;
#pragma unroll
            for (int j = 0; j < 4; j++) {
                int idx = tid + 256 * j;
                int r = idx >> 3, c = idx & 7;
                *(float4*)&Abuf[nb][r * 36 + c * 4] = make_float4(
                    __uint_as_float(f2tf(la[j].x)), __uint_as_float(f2tf(la[j].y)),
                    __uint_as_float(f2tf(la[j].z)), __uint_as_float(f2tf(la[j].w)));
                *(float4*)&Bbuf[nb][r * 36 + c * 4] = make_float4(
                    __uint_as_float(f2tf(lb[j].x)), __uint_as_float(f2tf(lb[j].y)),
                    __uint_as_float(f2tf(lb[j].z)), __uint_as_float(f2tf(lb[j].w)));
            }
            __syncthreads();
        }
    }
    // epilogue
#pragma unroll
    for (int am = 0; am < 2; am++) {
        int m0 = bm + wm + am * 16 + (lane >> 2);
#pragma unroll
        for (int bb = 0; bb < 8; bb++) {
            int n0 = bn + wn + bb * 8 + 2 * (lane & 3);
            float b0 = 0.f, b1 = 0.f;
            if (HASBIAS) { b0 = bi[n0]; b1 = bi[n0 + 1]; }
            float2 o0, o1;
            o0.x = acc[am][bb][0] * alpha + b0;
            o0.y = acc[am][bb][1] * alpha + b1;
            o1.x = acc[am][bb][2] * alpha + b0;
            o1.y = acc[am][bb][3] * alpha + b1;
            *(float2*)&C[(size_t)m0 * ldc + n0] = o0;
            *(float2*)&C[(size_t)(m0 + 8) * ldc + n0] = o1;
        }
    }
}

// ---------------- row softmax (row length 4096) ----------------
__global__ __launch_bounds__(256)
void softmax_rows(float* __restrict__ S_) {
    float* row = S_ + (size_t)blockIdx.x * SEQ;
    int t = threadIdx.x;
    __shared__ float red[256];
    float vals[16];
    float vmax = -1e30f;
#pragma unroll
    for (int i = 0; i < 16; i++) {
        vals[i] = row[t + i * 256];
        vmax = fmaxf(vmax, vals[i]);
    }
    red[t] = vmax;
    __syncthreads();
    for (int s = 128; s > 0; s >>= 1) {
        if (t < s) red[t] = fmaxf(red[t], red[t + s]);
        __syncthreads();
    }
    vmax = red[0];
    __syncthreads();
    float sum = 0.f;
#pragma unroll
    for (int i = 0; i < 16; i++) {
        vals[i] = __expf(vals[i] - vmax);
        sum += vals[i];
    }
    red[t] = sum;
    __syncthreads();
    for (int s = 128; s > 0; s >>= 1) {
        if (t < s) red[t] += red[t + s];
        __syncthreads();
    }
    float inv = 1.0f / red[0];
#pragma unroll
    for (int i = 0; i < 16; i++) row[t + i * 256] = vals[i] * inv;
}

// ---------------- residual + LayerNorm ----------------
__global__ __launch_bounds__(256)
void add_ln(const float* __restrict__ x, const float* __restrict__ y0,
            const float* __restrict__ gam, const float* __restrict__ bet,
            float* __restrict__ y) {
    int s = blockIdx.x, t = threadIdx.x;
    float v = x[s * H + t] + y0[s * H + t];
    __shared__ float red[256];
    red[t] = v;
    __syncthreads();
    for (int k = 128; k > 0; k >>= 1) {
        if (t < k) red[t] += red[t + k];
        __syncthreads();
    }
    float mu = red[0] * (1.0f / H);
    __syncthreads();
    float d = v - mu;
    red[t] = d * d;
    __syncthreads();
    for (int k = 128; k > 0; k >>= 1) {
        if (t < k) red[t] += red[t + k];
        __syncthreads();
    }
    float var = red[0] * (1.0f / H);
    y[s * H + t] = d * rsqrtf(var + 1e-5f) * gam[t] + bet[t];
}

// ---------------- GRU: 8-CTA cluster, mbarrier sync, triple-buffered h ----------------
// CTA rank owns units [rank*32, rank*32+32). thread=(g,s_): g unit, s_ 32-col segment.
// Producers (s_==0) broadcast h2 to all peers' hbuf[wb] then remote-arrive on each
// peer's mbarrier (expect 256 = 32 producers x 8 CTAs). Every warp contains producer
// lanes -> inter-warp skew <= 1 step -> triple buffering is race-free.
__global__ void __cluster_dims__(CLUSTER_N, 1, 1) __launch_bounds__(256, 1)
gru_kernel(const float* __restrict__ gi, const float* __restrict__ W_hh,
           const float* __restrict__ b_hh, float* __restrict__ hT) {
    __shared__ __align__(16) float hbuf[3][H];
    __shared__ __align__(8) uint64_t hbar;
    uint32_t rank;
    asm("mov.u32 %0, %%cluster_ctarank;" : "=r"(rank));
    const int t = threadIdx.x;
    const int g = t >> 3;
    const int s_ = t & 7;
    const int u = rank * 32 + g;

    float4 w[3][8];
#pragma unroll
    for (int r = 0; r < 3; r++) {
        const float4* Wrow = (const float4*)(W_hh + (size_t)(r * 256 + u) * H);
#pragma unroll
        for (int j = 0; j < 8; j++) {
            int jj = (j + s_) & 7;
            w[r][j] = Wrow[s_ * 8 + jj];
        }
    }
    float bhr = 0.f, bhz = 0.f, bhn = 0.f;
    if (s_ == 0) {
        bhr = b_hh[u];
        bhz = b_hh[256 + u];
        bhn = b_hh[512 + u];
    }
    if (t < H) { hbuf[0][t] = 0.f; hbuf[1][t] = 0.f; hbuf[2][t] = 0.f; }

    uint32_t bar_local = smem_to_u32(&hbar);
    if (t == 0) MBARRIER_INIT(bar_local, 32 * CLUSTER_N);
    uint32_t h_local = smem_to_u32(hbuf);
    uint32_t peer_h[CLUSTER_N], peer_b[CLUSTER_N];
#pragma unroll
    for (int d = 0; d < CLUSTER_N; d++) {
        asm("mapa.shared::cluster.u32 %0, %1, %2;"
            : "=r"(peer_h[d]) : "r"(h_local), "r"(d));
        asm("mapa.shared::cluster.u32 %0, %1, %2;"
            : "=r"(peer_b[d]) : "r"(bar_local), "r"(d));
    }
    asm volatile("barrier.cluster.arrive.aligned;" ::: "memory");
    asm volatile("barrier.cluster.wait.aligned;" ::: "memory");

    // gi prefetch (one step ahead)
    float gr_n = 0.f, gz_n = 0.f, gn_n = 0.f;
    if (s_ == 0) {
        gr_n = __ldg(gi + u);
        gz_n = __ldg(gi + 256 + u);
        gn_n = __ldg(gi + 512 + u);
    }
    int pb = 0;
    float hlast = 0.f;
    for (int step = 0; step < SEQ; step++) {
        float grc = gr_n, gzc = gz_n, gnc = gn_n;
        if (s_ == 0 && step + 1 < SEQ) {
            const float* gp = gi + (size_t)(step + 1) * G3H;
            gr_n = __ldg(gp + u);
            gz_n = __ldg(gp + 256 + u);
            gn_n = __ldg(gp + 512 + u);
        }
        if (step > 0) MBAR_WAIT_PARITY_CLUSTER(bar_local, (step - 1) & 1);

        float ar = 0.f, az = 0.f, an = 0.f;
        const float4* h4 = (const float4*)hbuf[pb];
#pragma unroll
        for (int j = 0; j < 8; j++) {
            int jj = (j + s_) & 7;
            float4 hv = h4[s_ * 8 + jj];
            ar += hv.x * w[0][j].x + hv.y * w[0][j].y + hv.z * w[0][j].z + hv.w * w[0][j].w;
            az += hv.x * w[1][j].x + hv.y * w[1][j].y + hv.z * w[1][j].z + hv.w * w[1][j].w;
            an += hv.x * w[2][j].x + hv.y * w[2][j].y + hv.z * w[2][j].z + hv.w * w[2][j].w;
        }
#pragma unroll
        for (int off = 4; off > 0; off >>= 1) {
            ar += __shfl_down_sync(0xffffffffu, ar, off);
            az += __shfl_down_sync(0xffffffffu, az, off);
            an += __shfl_down_sync(0xffffffffu, an, off);
        }
        int wb = pb + 1;
        if (wb == 3) wb = 0;
        if (s_ == 0) {
            float r = 1.f / (1.f + __expf(-(grc + ar + bhr)));
            float z = 1.f / (1.f + __expf(-(gzc + az + bhz)));
            float n = tanhf(gnc + r * (an + bhn));
            float hp = hbuf[pb][u];
            float h2 = (1.f - z) * n + z * hp;
            hlast = h2;
            uint32_t off = (uint32_t)((wb * H + u) * 4);
            uint32_t bits = __float_as_uint(h2);
#pragma unroll
            for (int d = 0; d < CLUSTER_N; d++) {
                asm volatile("st.shared::cluster.u32 [%0], %1;"
                             :: "r"(peer_h[d] + off), "r"(bits));
            }
#pragma unroll
            for (int d = 0; d < CLUSTER_N; d++) {
                MBAR_ARRIVE_REL_CLUSTER(peer_b[d]);
            }
        }
        pb = wb;
    }
    if (s_ == 0) hT[u] = hlast;
    asm volatile("barrier.cluster.arrive.aligned;" ::: "memory");
    asm volatile("barrier.cluster.wait.aligned;" ::: "memory");
}

// ---------------- output copy ----------------
__global__ void write_out(const float* __restrict__ hT, float* __restrict__ out,
                          int n) {
    int i = blockIdx.x * 256 + threadIdx.x;
    if (i < n) out[i] = hT[i & (H - 1)];
}

// ---------------- host launcher ----------------
extern "C" void kernel_launch(void* const* d_in, const int* in_sizes, int n_in,
                              void* d_out, int out_size) {
    const int* tokens = (const int*)d_in[0];
    const float* emb = (const float*)d_in[1];
    const float* Wq = (const float*)d_in[2];
    const float* bq = (const float*)d_in[3];
    const float* Wk = (const float*)d_in[4];
    const float* bk = (const float*)d_in[5];
    const float* Wv = (const float*)d_in[6];
    const float* bv = (const float*)d_in[7];
    const float* Wo = (const float*)d_in[8];
    const float* bo = (const float*)d_in[9];
    const float* ln_g = (const float*)d_in[10];
    const float* ln_b = (const float*)d_in[11];
    const float* W_ih = (const float*)d_in[12];
    const float* W_hh = (const float*)d_in[13];
    const float* b_ih = (const float*)d_in[14];
    const float* b_hh = (const float*)d_in[15];

    void* p;
    float *px, *pq, *pk, *pv, *pvt, *ps, *poc, *py0, *py, *pgi, *phT;
    float *pwqt, *pwkt, *pwvt, *pwot;
    cudaGetSymbolAddress(&p, g_x); px = (float*)p;
    cudaGetSymbolAddress(&p, g_q); pq = (float*)p;
    cudaGetSymbolAddress(&p, g_k); pk = (float*)p;
    cudaGetSymbolAddress(&p, g_v); pv = (float*)p;
    cudaGetSymbolAddress(&p, g_vt); pvt = (float*)p;
    cudaGetSymbolAddress(&p, g_scores); ps = (float*)p;
    cudaGetSymbolAddress(&p, g_oc); poc = (float*)p;
    cudaGetSymbolAddress(&p, g_y0); py0 = (float*)p;
    cudaGetSymbolAddress(&p, g_y); py = (float*)p;
    cudaGetSymbolAddress(&p, g_gi); pgi = (float*)p;
    cudaGetSymbolAddress(&p, g_hT); phT = (float*)p;
    cudaGetSymbolAddress(&p, g_wqt); pwqt = (float*)p;
    cudaGetSymbolAddress(&p, g_wkt); pwkt = (float*)p;
    cudaGetSymbolAddress(&p, g_wvt); pwvt = (float*)p;
    cudaGetSymbolAddress(&p, g_wot); pwot = (float*)p;

    cudaFuncSetAttribute(mma_nt<true>,
                         cudaFuncAttributeMaxDynamicSharedMemorySize, SMEM_MMA);
    cudaFuncSetAttribute(mma_nt<false>,
                         cudaFuncAttributeMaxDynamicSharedMemorySize, SMEM_MMA);

    const long long SH = (long long)SEQ * H;
    const long long SS = (long long)SEQ * SEQ;
    const long long HH = (long long)H * H;
    const float inv_scale = 1.0f / 16.0f;  // 1/sqrt(256)

    // 1) embedding
    embed_kernel<<<SEQ, H>>>(tokens, emb, px);

    // 2) weight transposes (to make every GEMM the NT mma path)
    dim3 gtw(H / 32, H / 32, NHEADS);
    transpose_k<<<gtw, 256>>>(Wq, pwqt, H, H, HH, HH);
    transpose_k<<<gtw, 256>>>(Wk, pwkt, H, H, HH, HH);
    transpose_k<<<gtw, 256>>>(Wv, pwvt, H, H, HH, HH);
    dim3 gtwo(H / 32, NHEADS * H / 32, 1);
    transpose_k<<<gtwo, 256>>>(Wo, pwot, NHEADS * H, H, 0, 0);

    // 3) per-head Q/K/V projections: x @ Wq[h]  (B = Wq[h]^T)
    dim3 gqkv(H / 128, SEQ / 128, NHEADS);
    mma_nt<true><<<gqkv, 256, SMEM_MMA>>>(px, pwqt, bq, pq, H, H, H, H,
                                          0, HH, H, SH, 1.f);
    mma_nt<true><<<gqkv, 256, SMEM_MMA>>>(px, pwkt, bk, pk, H, H, H, H,
                                          0, HH, H, SH, 1.f);
    mma_nt<true><<<gqkv, 256, SMEM_MMA>>>(px, pwvt, bv, pv, H, H, H, H,
                                          0, HH, H, SH, 1.f);

    // 3b) V transpose for the AV GEMM
    dim3 gtv(H / 32, SEQ / 32, NHEADS);
    transpose_k<<<gtv, 256>>>(pv, pvt, SEQ, H, SH, SH);

    // 4) scores = Q @ K^T / 16
    dim3 gsc(SEQ / 128, SEQ / 128, NHEADS);
    mma_nt<false><<<gsc, 256, SMEM_MMA>>>(pq, pk, nullptr, ps, H, H, H, SEQ,
                                          SH, SH, 0, SS, inv_scale);

    // 5) softmax
    softmax_rows<<<NHEADS * SEQ, 256>>>(ps);

    // 6) O = A @ V (B = Vt), written into concat layout [S, NH*H]
    dim3 gav(H / 128, SEQ / 128, NHEADS);
    mma_nt<false><<<gav, 256, SMEM_MMA>>>(ps, pvt, nullptr, poc, SEQ, SEQ, SEQ,
                                          NHEADS * H, SS, (long long)H * SEQ, 0,
                                          (long long)H, 1.f);

    // 7) output projection (B = Wo^T)
    dim3 gop(H / 128, SEQ / 128, 1);
    mma_nt<true><<<gop, 256, SMEM_MMA>>>(poc, pwot, bo, py0, NHEADS * H,
                                         NHEADS * H, NHEADS * H, H,
                                         0, 0, 0, 0, 1.f);

    // 8) residual + LayerNorm
    add_ln<<<SEQ, H>>>(px, py0, ln_g, ln_b, py);

    // 9) GRU input gates: y @ W_ih^T + b_ih  (W_ih already [N,K])
    dim3 ggi(G3H / 128, SEQ / 128, 1);
    mma_nt<true><<<ggi, 256, SMEM_MMA>>>(py, W_ih, b_ih, pgi, H, H, H, G3H,
                                         0, 0, 0, 0, 1.f);

    // 10) sequential GRU across 8-CTA cluster
    gru_kernel<<<CLUSTER_N, 256>>>(pgi, W_hh, b_hh, phT);

    // 11) output
    write_out<<<(out_size + 255) / 256, 256>>>(phT, (float*)d_out, out_size);
}

// round 4
// speedup vs baseline: 2.2369x; 2.2369x over previous
#include <cuda_runtime.h>
#include <cstdint>
#include <cstddef>

#define H 256
#define NHEADS 6
#define SEQ 4096
#define G3H 768
#define CLUSTER_N 8

// ================= helpers =================
__device__ __forceinline__ uint32_t smem_to_u32(const void* smem_ptr) {
    uint32_t addr;
    asm("{ .reg .u64 tmp; cvta.to.shared.u64 tmp, %1; cvt.u32.u64 %0, tmp; }"
        : "=r"(addr) : "l"(smem_ptr));
    return addr;
}
__device__ __forceinline__ uint32_t f2tf(float v) {
    uint32_t o;
    asm("cvt.rna.tf32.f32 %0, %1;" : "=r"(o) : "f"(v));
    return o;
}
__device__ __forceinline__ uint64_t packf2(float lo, float hi) {
    uint64_t u;
    asm("mov.b64 %0, {%1, %2};" : "=l"(u) : "f"(lo), "f"(hi));
    return u;
}
__device__ __forceinline__ uint64_t ffma2(uint64_t a, uint64_t b, uint64_t c) {
    uint64_t d;
    asm("fma.rn.f32x2 %0, %1, %2, %3;" : "=l"(d) : "l"(a), "l"(b), "l"(c));
    return d;
}
__device__ __forceinline__ float hsum2(uint64_t p) {
    float lo, hi;
    asm("mov.b64 {%0, %1}, %2;" : "=f"(lo), "=f"(hi) : "l"(p));
    return lo + hi;
}

#define MMA_TF32(d, a, b) \
    asm volatile("mma.sync.aligned.m16n8k8.row.col.f32.tf32.tf32.f32 " \
        "{%0,%1,%2,%3}, {%4,%5,%6,%7}, {%8,%9}, {%0,%1,%2,%3};" \
        : "+f"((d)[0]), "+f"((d)[1]), "+f"((d)[2]), "+f"((d)[3]) \
        : "r"((a)[0]), "r"((a)[1]), "r"((a)[2]), "r"((a)[3]), \
          "r"((b)[0]), "r"((b)[1]))

// ---------------- device scratch ----------------
__device__ float g_x[SEQ * H];
__device__ float g_q[NHEADS * SEQ * H];
__device__ float g_k[NHEADS * SEQ * H];
__device__ float g_v[NHEADS * SEQ * H];
__device__ float g_vt[NHEADS * H * SEQ];
__device__ float g_scores[(size_t)NHEADS * SEQ * SEQ];   // 402 MB
__device__ float g_oc[SEQ * NHEADS * H];
__device__ float g_y0[SEQ * H];
__device__ float g_y[SEQ * H];
__device__ float g_gi[SEQ * G3H];
__device__ float g_hT[H];
__device__ float g_wqt[NHEADS * H * H];
__device__ float g_wkt[NHEADS * H * H];
__device__ float g_wvt[NHEADS * H * H];
__device__ float g_wot[H * NHEADS * H];

// ---------------- embedding gather ----------------
__global__ void embed_kernel(const int* __restrict__ tok,
                             const float* __restrict__ emb,
                             float* __restrict__ x) {
    int s = blockIdx.x, d = threadIdx.x;
    x[s * H + d] = emb[(size_t)tok[s] * H + d];
}

// ---------------- generic batched transpose: out[C][R] = in[R][C] ----------------
__global__ __launch_bounds__(256)
void transpose_k(const float* __restrict__ in, float* __restrict__ out,
                 int R, int C, long long sI, long long sO) {
    __shared__ float tile[32][33];
    in += (long long)blockIdx.z * sI;
    out += (long long)blockIdx.z * sO;
    int r0 = blockIdx.y * 32, c0 = blockIdx.x * 32;
    int tx = threadIdx.x & 31, ty = threadIdx.x >> 5;
#pragma unroll
    for (int i = 0; i < 32; i += 8)
        tile[ty + i][tx] = in[(size_t)(r0 + ty + i) * C + c0 + tx];
    __syncthreads();
#pragma unroll
    for (int i = 0; i < 32; i += 8)
        out[(size_t)(c0 + ty + i) * R + r0 + tx] = tile[tx][ty + i];
}

// ================= tf32 mma.sync GEMM: C = alpha*(A @ B^T) (+bias) =================
// A: [M,K] lda, B: [N,K] ldb, fp32. CTA tile 128x128, K-tile 32, 8 warps (4x2),
// warp tile 32x64 = 2x8 m16n8k8 atoms. SMEM row stride 36 floats (conflict-free).
#define SMEM_MMA (4 * 128 * 36 * 4)   // 73728 B

template <bool HASBIAS>
__global__ __launch_bounds__(256)
void mma_nt(const float* __restrict__ A, const float* __restrict__ B,
            const float* __restrict__ bias, float* __restrict__ C,
            int K, int lda, int ldb, int ldc,
            long long sA, long long sB, long long sBias, long long sC,
            float alpha) {
    extern __shared__ float sm[];
    float* Abuf[2] = {sm, sm + 128 * 36};
    float* Bbuf[2] = {sm + 2 * 128 * 36, sm + 3 * 128 * 36};
    const int bz = blockIdx.z;
    A += (long long)bz * sA;
    B += (long long)bz * sB;
    C += (long long)bz * sC;
    const float* bi = nullptr;
    if (HASBIAS) bi = bias + (long long)bz * sBias;
    const int bm = blockIdx.y * 128, bn = blockIdx.x * 128;
    const int tid = threadIdx.x, lane = tid & 31, wid = tid >> 5;
    const int wm = (wid & 3) * 32, wn = (wid >> 2) * 64;

    float acc[2][8][4];
#pragma unroll
    for (int i = 0; i < 2; i++)
#pragma unroll
        for (int j = 0; j < 8; j++)
#pragma unroll
            for (int q = 0; q < 4; q++) acc[i][j][q] = 0.f;

    float4 la[4], lb[4];
    // prologue: stage k-tile 0 into buffer 0
    {
#pragma unroll
        for (int j = 0; j < 4; j++) {
            int idx = tid + 256 * j;
            int r = idx >> 3, c = idx & 7;
            la[j] = *(const float4*)(A + (size_t)(bm + r) * lda + c * 4);
            lb[j] = *(const float4*)(B + (size_t)(bn + r) * ldb + c * 4);
        }
#pragma unroll
        for (int j = 0; j < 4; j++) {
            int idx = tid + 256 * j;
            int r = idx >> 3, c = idx & 7;
            *(float4*)&Abuf[0][r * 36 + c * 4] = make_float4(
                __uint_as_float(f2tf(la[j].x)), __uint_as_float(f2tf(la[j].y)),
                __uint_as_float(f2tf(la[j].z)), __uint_as_float(f2tf(la[j].w)));
            *(float4*)&Bbuf[0][r * 36 + c * 4] = make_float4(
                __uint_as_float(f2tf(lb[j].x)), __uint_as_float(f2tf(lb[j].y)),
                __uint_as_float(f2tf(lb[j].z)), __uint_as_float(f2tf(lb[j].w)));
        }
        __syncthreads();
    }

    const int nkt = K >> 5;
    for (int kt = 0; kt < nkt; kt++) {
        const int cur = kt & 1;
        if (kt + 1 < nkt) {
            const int k0 = (kt + 1) * 32;
#pragma unroll
            for (int j = 0; j < 4; j++) {
                int idx = tid + 256 * j;
                int r = idx >> 3, c = idx & 7;
                la[j] = *(const float4*)(A + (size_t)(bm + r) * lda + k0 + c * 4);
                lb[j] = *(const float4*)(B + (size_t)(bn + r) * ldb + k0 + c * 4);
            }
        }
        const float* Ab = Abuf[cur];
        const float* Bb = Bbuf[cur];
        const int r0 = wm + (lane >> 2), qq = lane & 3;
#pragma unroll
        for (int ks = 0; ks < 4; ks++) {
            const int k0 = ks * 8 + qq;
            uint32_t af[2][4];
#pragma unroll
            for (int am = 0; am < 2; am++) {
                int rb = (r0 + am * 16) * 36;
                af[am][0] = __float_as_uint(Ab[rb + k0]);
                af[am][1] = __float_as_uint(Ab[rb + 8 * 36 + k0]);
                af[am][2] = __float_as_uint(Ab[rb + k0 + 4]);
                af[am][3] = __float_as_uint(Ab[rb + 8 * 36 + k0 + 4]);
            }
#pragma unroll
            for (int bb = 0; bb < 8; bb++) {
                int nb = (wn + bb * 8 + (lane >> 2)) * 36;
                uint32_t bf[2] = {__float_as_uint(Bb[nb + k0]),
                                  __float_as_uint(Bb[nb + k0 + 4])};
                MMA_TF32(acc[0][bb], af[0], bf);
                MMA_TF32(acc[1][bb], af[1], bf);
            }
        }
        if (kt + 1 < nkt) {
            const int nb = (kt + 1) & 1;
#pragma unroll
            for (int j = 0; j < 4; j++) {
                int idx = tid + 256 * j;
                int r = idx >> 3, c = idx & 7;
                *(float4*)&Abuf[nb][r * 36 + c * 4] = make_float4(
                    __uint_as_float(f2tf(la[j].x)), __uint_as_float(f2tf(la[j].y)),
                    __uint_as_float(f2tf(la[j].z)), __uint_as_float(f2tf(la[j].w)));
                *(float4*)&Bbuf[nb][r * 36 + c * 4] = make_float4(
                    __uint_as_float(f2tf(lb[j].x)), __uint_as_float(f2tf(lb[j].y)),
                    __uint_as_float(f2tf(lb[j].z)), __uint_as_float(f2tf(lb[j].w)));
            }
            __syncthreads();
        }
    }
    // epilogue
#pragma unroll
    for (int am = 0; am < 2; am++) {
        int m0 = bm + wm + am * 16 + (lane >> 2);
#pragma unroll
        for (int bb = 0; bb < 8; bb++) {
            int n0 = bn + wn + bb * 8 + 2 * (lane & 3);
            float b0 = 0.f, b1 = 0.f;
            if (HASBIAS) { b0 = bi[n0]; b1 = bi[n0 + 1]; }
            float2 o0, o1;
            o0.x = acc[am][bb][0] * alpha + b0;
            o0.y = acc[am][bb][1] * alpha + b1;
            o1.x = acc[am][bb][2] * alpha + b0;
            o1.y = acc[am][bb][3] * alpha + b1;
            *(float2*)&C[(size_t)m0 * ldc + n0] = o0;
            *(float2*)&C[(size_t)(m0 + 8) * ldc + n0] = o1;
        }
    }
}

// ---------------- row softmax (row length 4096) ----------------
__global__ __launch_bounds__(256)
void softmax_rows(float* __restrict__ S_) {
    float* row = S_ + (size_t)blockIdx.x * SEQ;
    int t = threadIdx.x;
    __shared__ float red[256];
    float vals[16];
    float vmax = -1e30f;
#pragma unroll
    for (int i = 0; i < 16; i++) {
        vals[i] = row[t + i * 256];
        vmax = fmaxf(vmax, vals[i]);
    }
    red[t] = vmax;
    __syncthreads();
    for (int s = 128; s > 0; s >>= 1) {
        if (t < s) red[t] = fmaxf(red[t], red[t + s]);
        __syncthreads();
    }
    vmax = red[0];
    __syncthreads();
    float sum = 0.f;
#pragma unroll
    for (int i = 0; i < 16; i++) {
        vals[i] = __expf(vals[i] - vmax);
        sum += vals[i];
    }
    red[t] = sum;
    __syncthreads();
    for (int s = 128; s > 0; s >>= 1) {
        if (t < s) red[t] += red[t + s];
        __syncthreads();
    }
    float inv = 1.0f / red[0];
#pragma unroll
    for (int i = 0; i < 16; i++) row[t + i * 256] = vals[i] * inv;
}

// ---------------- residual + LayerNorm ----------------
__global__ __launch_bounds__(256)
void add_ln(const float* __restrict__ x, const float* __restrict__ y0,
            const float* __restrict__ gam, const float* __restrict__ bet,
            float* __restrict__ y) {
    int s = blockIdx.x, t = threadIdx.x;
    float v = x[s * H + t] + y0[s * H + t];
    __shared__ float red[256];
    red[t] = v;
    __syncthreads();
    for (int k = 128; k > 0; k >>= 1) {
        if (t < k) red[t] += red[t + k];
        __syncthreads();
    }
    float mu = red[0] * (1.0f / H);
    __syncthreads();
    float d = v - mu;
    red[t] = d * d;
    __syncthreads();
    for (int k = 128; k > 0; k >>= 1) {
        if (t < k) red[t] += red[t + k];
        __syncthreads();
    }
    float var = red[0] * (1.0f / H);
    y[s * H + t] = d * rsqrtf(var + 1e-5f) * gam[t] + bet[t];
}

// ---------------- GRU: 8-CTA cluster, barrier.cluster sync, FFMA2 math ----------------
// R1 design (hardware cluster barrier per step, double-buffered h) + packed f32x2
// dot products (halves FMA issue count) + one-step-ahead gi prefetch.
__global__ void __cluster_dims__(CLUSTER_N, 1, 1) __launch_bounds__(256, 1)
gru_kernel(const float* __restrict__ gi, const float* __restrict__ W_hh,
           const float* __restrict__ b_hh, float* __restrict__ hT) {
    __shared__ __align__(16) float hbuf[2][H];
    uint32_t rank;
    asm("mov.u32 %0, %%cluster_ctarank;" : "=r"(rank));
    const int t = threadIdx.x;
    const int g = t >> 3;
    const int s_ = t & 7;
    const int u = rank * 32 + g;

    // packed W_hh rows for units {u, 256+u, 512+u}, columns [s_*32, s_*32+32)
    uint64_t wp[3][8][2];
#pragma unroll
    for (int r = 0; r < 3; r++) {
        const float4* Wrow = (const float4*)(W_hh + (size_t)(r * 256 + u) * H);
#pragma unroll
        for (int j = 0; j < 8; j++) {
            int jj = (j + s_) & 7;
            float4 w4 = Wrow[s_ * 8 + jj];
            wp[r][j][0] = packf2(w4.x, w4.y);
            wp[r][j][1] = packf2(w4.z, w4.w);
        }
    }
    float bhr = 0.f, bhz = 0.f, bhn = 0.f;
    if (s_ == 0) {
        bhr = b_hh[u];
        bhz = b_hh[256 + u];
        bhn = b_hh[512 + u];
    }
    if (t < H) { hbuf[0][t] = 0.f; hbuf[1][t] = 0.f; }

    uint32_t local_base = smem_to_u32(hbuf);
    uint32_t peer_addr[CLUSTER_N];
#pragma unroll
    for (int d = 0; d < CLUSTER_N; d++) {
        asm("mapa.shared::cluster.u32 %0, %1, %2;"
            : "=r"(peer_addr[d]) : "r"(local_base), "r"(d));
    }

    asm volatile("barrier.cluster.arrive.aligned;" ::: "memory");
    asm volatile("barrier.cluster.wait.aligned;" ::: "memory");

    // gi prefetch (one step ahead)
    float gr_n = 0.f, gz_n = 0.f, gn_n = 0.f;
    if (s_ == 0) {
        gr_n = __ldg(gi + u);
        gz_n = __ldg(gi + 256 + u);
        gn_n = __ldg(gi + 512 + u);
    }
    const uint64_t z64 = packf2(0.f, 0.f);
    for (int step = 0; step < SEQ; step++) {
        const int p = step & 1;
        float grc = gr_n, gzc = gz_n, gnc = gn_n;
        if (s_ == 0 && step + 1 < SEQ) {
            const float* gp = gi + (size_t)(step + 1) * G3H;
            gr_n = __ldg(gp + u);
            gz_n = __ldg(gp + 256 + u);
            gn_n = __ldg(gp + 512 + u);
        }
        uint64_t pr = z64, pz = z64, pn = z64;
        const float4* h4 = (const float4*)hbuf[p];
#pragma unroll
        for (int j = 0; j < 8; j++) {
            int jj = (j + s_) & 7;
            float4 hv = h4[s_ * 8 + jj];
            uint64_t h01 = packf2(hv.x, hv.y);
            uint64_t h23 = packf2(hv.z, hv.w);
            pr = ffma2(h01, wp[0][j][0], pr);
            pz = ffma2(h01, wp[1][j][0], pz);
            pn = ffma2(h01, wp[2][j][0], pn);
            pr = ffma2(h23, wp[0][j][1], pr);
            pz = ffma2(h23, wp[1][j][1], pz);
            pn = ffma2(h23, wp[2][j][1], pn);
        }
        float ar = hsum2(pr), az = hsum2(pz), an = hsum2(pn);
#pragma unroll
        for (int off = 4; off > 0; off >>= 1) {
            ar += __shfl_down_sync(0xffffffffu, ar, off);
            az += __shfl_down_sync(0xffffffffu, az, off);
            an += __shfl_down_sync(0xffffffffu, an, off);
        }
        if (s_ == 0) {
            float r = 1.f / (1.f + __expf(-(grc + ar + bhr)));
            float z = 1.f / (1.f + __expf(-(gzc + az + bhz)));
            float n = tanhf(gnc + r * (an + bhn));
            float hp = hbuf[p][u];
            float h2 = (1.f - z) * n + z * hp;
            uint32_t off = (uint32_t)(((p ^ 1) * H + u) * 4);
            uint32_t bits = __float_as_uint(h2);
#pragma unroll
            for (int d = 0; d < CLUSTER_N; d++) {
                asm volatile("st.shared::cluster.u32 [%0], %1;"
                             :: "r"(peer_addr[d] + off), "r"(bits));
            }
        }
        asm volatile("barrier.cluster.arrive.aligned;" ::: "memory");
        asm volatile("barrier.cluster.wait.aligned;" ::: "memory");
    }
    // SEQ even -> final h lives in hbuf[0]
    if (t < 32) hT[rank * 32 + t] = hbuf[0][rank * 32 + t];
}

// ---------------- output copy ----------------
__global__ void write_out(const float* __restrict__ hT, float* __restrict__ out,
                          int n) {
    int i = blockIdx.x * 256 + threadIdx.x;
    if (i < n) out[i] = hT[i & (H - 1)];
}

// ---------------- host launcher ----------------
extern "C" void kernel_launch(void* const* d_in, const int* in_sizes, int n_in,
                              void* d_out, int out_size) {
    const int* tokens = (const int*)d_in[0];
    const float* emb = (const float*)d_in[1];
    const float* Wq = (const float*)d_in[2];
    const float* bq = (const float*)d_in[3];
    const float* Wk = (const float*)d_in[4];
    const float* bk = (const float*)d_in[5];
    const float* Wv = (const float*)d_in[6];
    const float* bv = (const float*)d_in[7];
    const float* Wo = (const float*)d_in[8];
    const float* bo = (const float*)d_in[9];
    const float* ln_g = (const float*)d_in[10];
    const float* ln_b = (const float*)d_in[11];
    const float* W_ih = (const float*)d_in[12];
    const float* W_hh = (const float*)d_in[13];
    const float* b_ih = (const float*)d_in[14];
    const float* b_hh = (const float*)d_in[15];

    void* p;
    float *px, *pq, *pk, *pv, *pvt, *ps, *poc, *py0, *py, *pgi, *phT;
    float *pwqt, *pwkt, *pwvt, *pwot;
    cudaGetSymbolAddress(&p, g_x); px = (float*)p;
    cudaGetSymbolAddress(&p, g_q); pq = (float*)p;
    cudaGetSymbolAddress(&p, g_k); pk = (float*)p;
    cudaGetSymbolAddress(&p, g_v); pv = (float*)p;
    cudaGetSymbolAddress(&p, g_vt); pvt = (float*)p;
    cudaGetSymbolAddress(&p, g_scores); ps = (float*)p;
    cudaGetSymbolAddress(&p, g_oc); poc = (float*)p;
    cudaGetSymbolAddress(&p, g_y0); py0 = (float*)p;
    cudaGetSymbolAddress(&p, g_y); py = (float*)p;
    cudaGetSymbolAddress(&p, g_gi); pgi = (float*)p;
    cudaGetSymbolAddress(&p, g_hT); phT = (float*)p;
    cudaGetSymbolAddress(&p, g_wqt); pwqt = (float*)p;
    cudaGetSymbolAddress(&p, g_wkt); pwkt = (float*)p;
    cudaGetSymbolAddress(&p, g_wvt); pwvt = (float*)p;
    cudaGetSymbolAddress(&p, g_wot); pwot = (float*)p;

    cudaFuncSetAttribute(mma_nt<true>,
                         cudaFuncAttributeMaxDynamicSharedMemorySize, SMEM_MMA);
    cudaFuncSetAttribute(mma_nt<false>,
                         cudaFuncAttributeMaxDynamicSharedMemorySize, SMEM_MMA);

    const long long SH = (long long)SEQ * H;
    const long long SS = (long long)SEQ * SEQ;
    const long long HH = (long long)H * H;
    const float inv_scale = 1.0f / 16.0f;  // 1/sqrt(256)

    // 1) embedding
    embed_kernel<<<SEQ, H>>>(tokens, emb, px);

    // 2) weight transposes (to make every GEMM the NT mma path)
    dim3 gtw(H / 32, H / 32, NHEADS);
    transpose_k<<<gtw, 256>>>(Wq, pwqt, H, H, HH, HH);
    transpose_k<<<gtw, 256>>>(Wk, pwkt, H, H, HH, HH);
    transpose_k<<<gtw, 256>>>(Wv, pwvt, H, H, HH, HH);
    dim3 gtwo(H / 32, NHEADS * H / 32, 1);
    transpose_k<<<gtwo, 256>>>(Wo, pwot, NHEADS * H, H, 0, 0);

    // 3) per-head Q/K/V projections: x @ Wq[h]  (B = Wq[h]^T)
    dim3 gqkv(H / 128, SEQ / 128, NHEADS);
    mma_nt<true><<<gqkv, 256, SMEM_MMA>>>(px, pwqt, bq, pq, H, H, H, H,
                                          0, HH, H, SH, 1.f);
    mma_nt<true><<<gqkv, 256, SMEM_MMA>>>(px, pwkt, bk, pk, H, H, H, H,
                                          0, HH, H, SH, 1.f);
    mma_nt<true><<<gqkv, 256, SMEM_MMA>>>(px, pwvt, bv, pv, H, H, H, H,
                                          0, HH, H, SH, 1.f);

    // 3b) V transpose for the AV GEMM
    dim3 gtv(H / 32, SEQ / 32, NHEADS);
    transpose_k<<<gtv, 256>>>(pv, pvt, SEQ, H, SH, SH);

    // 4) scores = Q @ K^T / 16
    dim3 gsc(SEQ / 128, SEQ / 128, NHEADS);
    mma_nt<false><<<gsc, 256, SMEM_MMA>>>(pq, pk, nullptr, ps, H, H, H, SEQ,
                                          SH, SH, 0, SS, inv_scale);

    // 5) softmax
    softmax_rows<<<NHEADS * SEQ, 256>>>(ps);

    // 6) O = A @ V (B = Vt), written into concat layout [S, NH*H]
    dim3 gav(H / 128, SEQ / 128, NHEADS);
    mma_nt<false><<<gav, 256, SMEM_MMA>>>(ps, pvt, nullptr, poc, SEQ, SEQ, SEQ,
                                          NHEADS * H, SS, (long long)H * SEQ, 0,
                                          (long long)H, 1.f);

    // 7) output projection (B = Wo^T)
    dim3 gop(H / 128, SEQ / 128, 1);
    mma_nt<true><<<gop, 256, SMEM_MMA>>>(poc, pwot, bo, py0, NHEADS * H,
                                         NHEADS * H, NHEADS * H, H,
                                         0, 0, 0, 0, 1.f);

    // 8) residual + LayerNorm
    add_ln<<<SEQ, H>>>(px, py0, ln_g, ln_b, py);

    // 9) GRU input gates: y @ W_ih^T + b_ih  (W_ih already [N,K])
    dim3 ggi(G3H / 128, SEQ / 128, 1);
    mma_nt<true><<<ggi, 256, SMEM_MMA>>>(py, W_ih, b_ih, pgi, H, H, H, G3H,
                                         0, 0, 0, 0, 1.f);

    // 10) sequential GRU across 8-CTA cluster
    gru_kernel<<<CLUSTER_N, 256>>>(pgi, W_hh, b_hh, phT);

    // 11) output
    write_out<<<(out_size + 255) / 256, 256>>>(phT, (float*)d_out, out_size);
}

// round 7
// speedup vs baseline: 4.0008x; 1.7886x over previous
#include <cuda_runtime.h>
#include <cuda_fp16.h>
#include <cstdint>
#include <cstddef>

#define H 256
#define NHEADS 6
#define SEQ 4096
#define G3H 768
#define CLUSTER_N 8

// ================= helpers =================
__device__ __forceinline__ uint32_t smem_to_u32(const void* smem_ptr) {
    uint32_t addr;
    asm("{ .reg .u64 tmp; cvta.to.shared.u64 tmp, %1; cvt.u32.u64 %0, tmp; }"
        : "=r"(addr) : "l"(smem_ptr));
    return addr;
}
__device__ __forceinline__ uint32_t packh2(float lo, float hi) {
    __half2 h = __floats2half2_rn(lo, hi);
    return *reinterpret_cast<uint32_t*>(&h);
}
__device__ __forceinline__ uint64_t packf2(float lo, float hi) {
    uint64_t u;
    asm("mov.b64 %0, {%1, %2};" : "=l"(u) : "f"(lo), "f"(hi));
    return u;
}
__device__ __forceinline__ uint64_t ffma2(uint64_t a, uint64_t b, uint64_t c) {
    uint64_t d;
    asm("fma.rn.f32x2 %0, %1, %2, %3;" : "=l"(d) : "l"(a), "l"(b), "l"(c));
    return d;
}
__device__ __forceinline__ float hsum2(uint64_t p) {
    float lo, hi;
    asm("mov.b64 {%0, %1}, %2;" : "=f"(lo), "=f"(hi) : "l"(p));
    return lo + hi;
}
#define MBARRIER_INIT(mbar, count) \
    asm volatile("mbarrier.init.shared.b64 [%0], %1;" \
                 :: "r"((uint32_t)(mbar)), "r"((uint32_t)(count)) : "memory")
#define MBARRIER_EXPECT_TX(mbar, tx) \
    asm volatile("mbarrier.arrive.expect_tx.shared.b64 _, [%0], %1;" \
                 :: "r"((uint32_t)(mbar)), "r"((uint32_t)(tx)) : "memory")
#define MBAR_WAIT_PARITY(mbar, parity) do { \
    uint32_t _m = (mbar), _p = (parity), _d; \
    asm volatile("{\n\t.reg .pred p;\n\t" \
        "mbarrier.try_wait.parity.shared.b64 p, [%1], %2;\n\t" \
        "selp.b32 %0,1,0,p;\n\t}" : "=r"(_d) : "r"(_m), "r"(_p) : "memory"); \
    if (!_d) { \
        asm volatile("{\n\t.reg .pred P1;\n\t" \
            "WL_%=:\n\t" \
            "mbarrier.try_wait.parity.shared.b64 P1, [%0], %1, 0x989680;\n\t" \
            "@P1 bra.uni WD_%=;\n\t" \
            "bra.uni WL_%=;\n\t" \
            "WD_%=:\n\t}" :: "r"(_m), "r"(_p) : "memory"); \
    } \
} while (0)
#define ST_ASYNC_U32(raddr, val, rbar) \
    asm volatile("st.async.shared::cluster.mbarrier::complete_tx::bytes.b32 [%0], %1, [%2];" \
                 :: "r"(raddr), "r"(val), "r"(rbar) : "memory")

#define MMA_F16(d, a, b) \
    asm volatile("mma.sync.aligned.m16n8k16.row.col.f32.f16.f16.f32 " \
        "{%0,%1,%2,%3}, {%4,%5,%6,%7}, {%8,%9}, {%0,%1,%2,%3};" \
        : "+f"((d)[0]), "+f"((d)[1]), "+f"((d)[2]), "+f"((d)[3]) \
        : "r"((a)[0]), "r"((a)[1]), "r"((a)[2]), "r"((a)[3]), \
          "r"((b)[0]), "r"((b)[1]))

// ---------------- device scratch ----------------
__device__ float  g_x[SEQ * H];
__device__ __half g_qh[NHEADS * SEQ * H];
__device__ __half g_kh[NHEADS * SEQ * H];
__device__ __half g_vh[NHEADS * SEQ * H];
__device__ __half g_vth[NHEADS * H * SEQ];
__device__ float  g_scores[(size_t)NHEADS * SEQ * SEQ];   // 402 MB
__device__ __half g_probs[(size_t)NHEADS * SEQ * SEQ];    // 201 MB
__device__ __half g_och[SEQ * NHEADS * H];
__device__ float  g_y0[SEQ * H];
__device__ float  g_y[SEQ * H];
__device__ float  g_gi[SEQ * G3H];
__device__ float  g_hT[H];
__device__ __half g_wqt[NHEADS * H * H];
__device__ __half g_wkt[NHEADS * H * H];
__device__ __half g_wvt[NHEADS * H * H];
__device__ __half g_wot[H * NHEADS * H];
__device__ __half g_wih[G3H * H];

// ---------------- embedding gather ----------------
__global__ void embed_kernel(const int* __restrict__ tok,
                             const float* __restrict__ emb,
                             float* __restrict__ x) {
    int s = blockIdx.x, d = threadIdx.x;
    x[s * H + d] = emb[(size_t)tok[s] * H + d];
}

// ---------------- transpose to half: out[C][R] = (half)in[R][C] ----------------
template <typename TI>
__global__ __launch_bounds__(256)
void transpose_h(const TI* __restrict__ in, __half* __restrict__ out,
                 int R, int C, long long sI, long long sO) {
    __shared__ float tile[32][33];
    in += (long long)blockIdx.z * sI;
    out += (long long)blockIdx.z * sO;
    int r0 = blockIdx.y * 32, c0 = blockIdx.x * 32;
    int tx = threadIdx.x & 31, ty = threadIdx.x >> 5;
#pragma unroll
    for (int i = 0; i < 32; i += 8)
        tile[ty + i][tx] = (float)in[(size_t)(r0 + ty + i) * C + c0 + tx];
    __syncthreads();
#pragma unroll
    for (int i = 0; i < 32; i += 8)
        out[(size_t)(c0 + ty + i) * R + r0 + tx] = __float2half_rn(tile[tx][ty + i]);
}

// ---------------- fp32 -> fp16 convert ----------------
__global__ void to_half(const float* __restrict__ in, __half* __restrict__ out,
                        int n) {
    int i = blockIdx.x * 256 + threadIdx.x;
    if (i < n) out[i] = __float2half_rn(in[i]);
}

// ================= fp16 mma.sync GEMM: C = alpha*(A @ B^T) (+bias) =================
// A: [M,K], B: [N,K]; AH/BH select fp16 vs fp32 source; OH selects fp16 vs fp32 out.
// CTA tile 128x128, K-tile 32, 8 warps (4x2), warp tile 32x64 = m16n8k16 atoms.
// SMEM rows: 16 uints (32 halfs) at stride 20 uints -> conflict-free fragment reads.
// Staging: half operand = 2 iters of uint4 (8 halfs), float operand = 4 iters of float4.
template <bool AH, bool BH, bool OH, bool HASBIAS>
__global__ __launch_bounds__(256)
void hgemm_nt(const void* __restrict__ Av, const void* __restrict__ Bv,
              const float* __restrict__ bias, void* __restrict__ Cv,
              int K, int lda, int ldb, int ldc,
              long long sA, long long sB, long long sBias, long long sC,
              float alpha) {
    __shared__ uint32_t smA[2][128 * 20];
    __shared__ uint32_t smB[2][128 * 20];
    const int bz = blockIdx.z;
    const float*  Afp = (const float*)Av + (AH ? 0 : (long long)bz * sA);
    const __half* Ahp = (const __half*)Av + (AH ? (long long)bz * sA : 0);
    const float*  Bfp = (const float*)Bv + (BH ? 0 : (long long)bz * sB);
    const __half* Bhp = (const __half*)Bv + (BH ? (long long)bz * sB : 0);
    float*  Cfp = (float*)Cv + (OH ? 0 : (long long)bz * sC);
    __half* Chp = (__half*)Cv + (OH ? (long long)bz * sC : 0);
    const float* bi = HASBIAS ? (bias + (long long)bz * sBias) : nullptr;

    const int bm = blockIdx.y * 128, bn = blockIdx.x * 128;
    const int tid = threadIdx.x, lane = tid & 31, wid = tid >> 5;
    const int wm = (wid & 3) * 32, wn = (wid >> 2) * 64;

    float acc[2][8][4];
#pragma unroll
    for (int i = 0; i < 2; i++)
#pragma unroll
        for (int j = 0; j < 8; j++)
#pragma unroll
            for (int q = 0; q < 4; q++) acc[i][j][q] = 0.f;

    float4 laf[4], lbf[4];
    uint4 lah[2], lbh[2];

    // ---- load k-tile (gmem -> regs) ----
#define LOAD_TILE(k0)                                                          \
    do {                                                                       \
        if (AH) {                                                              \
            _Pragma("unroll")                                                  \
            for (int i = 0; i < 2; i++) {                                      \
                int idx = tid + 256 * i;                                       \
                int r = idx >> 2, c = idx & 3;                                 \
                lah[i] = *(const uint4*)(Ahp + (size_t)(bm + r) * lda + (k0) + c * 8); \
            }                                                                  \
        } else {                                                               \
            _Pragma("unroll")                                                  \
            for (int i = 0; i < 4; i++) {                                      \
                int idx = tid + 256 * i;                                       \
                int r = idx >> 3, c = idx & 7;                                 \
                laf[i] = *(const float4*)(Afp + (size_t)(bm + r) * lda + (k0) + c * 4); \
            }                                                                  \
        }                                                                      \
        if (BH) {                                                              \
            _Pragma("unroll")                                                  \
            for (int i = 0; i < 2; i++) {                                      \
                int idx = tid + 256 * i;                                       \
                int r = idx >> 2, c = idx & 3;                                 \
                lbh[i] = *(const uint4*)(Bhp + (size_t)(bn + r) * ldb + (k0) + c * 8); \
            }                                                                  \
        } else {                                                               \
            _Pragma("unroll")                                                  \
            for (int i = 0; i < 4; i++) {                                      \
                int idx = tid + 256 * i;                                       \
                int r = idx >> 3, c = idx & 7;                                 \
                lbf[i] = *(const float4*)(Bfp + (size_t)(bn + r) * ldb + (k0) + c * 4); \
            }                                                                  \
        }                                                                      \
    } while (0)

    // ---- store staged regs to SMEM buffer `buf` ----
#define STORE_TILE(buf)                                                        \
    do {                                                                       \
        if (AH) {                                                              \
            _Pragma("unroll")                                                  \
            for (int i = 0; i < 2; i++) {                                      \
                int idx = tid + 256 * i;                                       \
                int r = idx >> 2, c = idx & 3;                                 \
                *(uint4*)&smA[buf][r * 20 + c * 4] = lah[i];                   \
            }                                                                  \
        } else {                                                               \
            _Pragma("unroll")                                                  \
            for (int i = 0; i < 4; i++) {                                      \
                int idx = tid + 256 * i;                                       \
                int r = idx >> 3, c = idx & 7;                                 \
                uint2 u = {packh2(laf[i].x, laf[i].y), packh2(laf[i].z, laf[i].w)}; \
                *(uint2*)&smA[buf][r * 20 + c * 2] = u;                        \
            }                                                                  \
        }                                                                      \
        if (BH) {                                                              \
            _Pragma("unroll")                                                  \
            for (int i = 0; i < 2; i++) {                                      \
                int idx = tid + 256 * i;                                       \
                int r = idx >> 2, c = idx & 3;                                 \
                *(uint4*)&smB[buf][r * 20 + c * 4] = lbh[i];                   \
            }                                                                  \
        } else {                                                               \
            _Pragma("unroll")                                                  \
            for (int i = 0; i < 4; i++) {                                      \
                int idx = tid + 256 * i;                                       \
                int r = idx >> 3, c = idx & 7;                                 \
                uint2 u = {packh2(lbf[i].x, lbf[i].y), packh2(lbf[i].z, lbf[i].w)}; \
                *(uint2*)&smB[buf][r * 20 + c * 2] = u;                        \
            }                                                                  \
        }                                                                      \
    } while (0)

    LOAD_TILE(0);
    STORE_TILE(0);
    __syncthreads();

    const int nkt = K >> 5;
    for (int kt = 0; kt < nkt; kt++) {
        const int cur = kt & 1;
        if (kt + 1 < nkt) LOAD_TILE((kt + 1) * 32);
        const uint32_t* Ab = smA[cur];
        const uint32_t* Bb = smB[cur];
        const int r0 = wm + (lane >> 2), qc = lane & 3;
#pragma unroll
        for (int ks = 0; ks < 2; ks++) {
            const int kc = ks * 8 + qc;
            uint32_t af[2][4];
#pragma unroll
            for (int am = 0; am < 2; am++) {
                int rb = (r0 + am * 16) * 20;
                af[am][0] = Ab[rb + kc];
                af[am][1] = Ab[rb + 8 * 20 + kc];
                af[am][2] = Ab[rb + kc + 4];
                af[am][3] = Ab[rb + 8 * 20 + kc + 4];
            }
#pragma unroll
            for (int bb = 0; bb < 8; bb++) {
                int nb = (wn + bb * 8 + (lane >> 2)) * 20;
                uint32_t bf[2] = {Bb[nb + kc], Bb[nb + kc + 4]};
                MMA_F16(acc[0][bb], af[0], bf);
                MMA_F16(acc[1][bb], af[1], bf);
            }
        }
        if (kt + 1 < nkt) {
            __syncthreads();   // everyone done reading smem[next] from 2 tiles ago
            STORE_TILE((kt + 1) & 1);
            __syncthreads();
        }
    }
    // ---- epilogue ----
#pragma unroll
    for (int am = 0; am < 2; am++) {
        int m0 = bm + wm + am * 16 + (lane >> 2);
#pragma unroll
        for (int bb = 0; bb < 8; bb++) {
            int n0 = bn + wn + bb * 8 + 2 * (lane & 3);
            float b0 = 0.f, b1 = 0.f;
            if (HASBIAS) { b0 = bi[n0]; b1 = bi[n0 + 1]; }
            float v0 = acc[am][bb][0] * alpha + b0;
            float v1 = acc[am][bb][1] * alpha + b1;
            float v2 = acc[am][bb][2] * alpha + b0;
            float v3 = acc[am][bb][3] * alpha + b1;
            if (OH) {
                *(uint32_t*)&Chp[(size_t)m0 * ldc + n0] = packh2(v0, v1);
                *(uint32_t*)&Chp[(size_t)(m0 + 8) * ldc + n0] = packh2(v2, v3);
            } else {
                *(float2*)&Cfp[(size_t)m0 * ldc + n0] = make_float2(v0, v1);
                *(float2*)&Cfp[(size_t)(m0 + 8) * ldc + n0] = make_float2(v2, v3);
            }
        }
    }
#undef LOAD_TILE
#undef STORE_TILE
}

// ---------------- row softmax: fp32 scores in, fp16 probs out ----------------
__global__ __launch_bounds__(256)
void softmax_rows(const float* __restrict__ S_, __half* __restrict__ P_) {
    const float* row = S_ + (size_t)blockIdx.x * SEQ;
    __half* prow = P_ + (size_t)blockIdx.x * SEQ;
    int t = threadIdx.x;
    __shared__ float red[256];
    float vals[16];
    float vmax = -1e30f;
#pragma unroll
    for (int i = 0; i < 16; i++) {
        vals[i] = row[t + i * 256];
        vmax = fmaxf(vmax, vals[i]);
    }
    red[t] = vmax;
    __syncthreads();
    for (int s = 128; s > 0; s >>= 1) {
        if (t < s) red[t] = fmaxf(red[t], red[t + s]);
        __syncthreads();
    }
    vmax = red[0];
    __syncthreads();
    float sum = 0.f;
#pragma unroll
    for (int i = 0; i < 16; i++) {
        vals[i] = __expf(vals[i] - vmax);
        sum += vals[i];
    }
    red[t] = sum;
    __syncthreads();
    for (int s = 128; s > 0; s >>= 1) {
        if (t < s) red[t] += red[t + s];
        __syncthreads();
    }
    float inv = 1.0f / red[0];
#pragma unroll
    for (int i = 0; i < 16; i++)
        prow[t + i * 256] = __float2half_rn(vals[i] * inv);
}

// ---------------- residual + LayerNorm ----------------
__global__ __launch_bounds__(256)
void add_ln(const float* __restrict__ x, const float* __restrict__ y0,
            const float* __restrict__ gam, const float* __restrict__ bet,
            float* __restrict__ y) {
    int s = blockIdx.x, t = threadIdx.x;
    float v = x[s * H + t] + y0[s * H + t];
    __shared__ float red[256];
    red[t] = v;
    __syncthreads();
    for (int k = 128; k > 0; k >>= 1) {
        if (t < k) red[t] += red[t + k];
        __syncthreads();
    }
    float mu = red[0] * (1.0f / H);
    __syncthreads();
    float d = v - mu;
    red[t] = d * d;
    __syncthreads();
    for (int k = 128; k > 0; k >>= 1) {
        if (t < k) red[t] += red[t + k];
        __syncthreads();
    }
    float var = red[0] * (1.0f / H);
    y[s * H + t] = d * rsqrtf(var + 1e-5f) * gam[t] + bet[t];
}

// ---------------- GRU: 8-CTA cluster, st.async + mbarrier tx sync ----------------
__global__ void __cluster_dims__(CLUSTER_N, 1, 1) __launch_bounds__(256, 1)
gru_kernel(const float* __restrict__ gi, const float* __restrict__ W_hh,
           const float* __restrict__ b_hh, float* __restrict__ hT) {
    __shared__ __align__(16) float hbuf[2][H];
    __shared__ __align__(8) uint64_t bars[2];
    uint32_t rank;
    asm("mov.u32 %0, %%cluster_ctarank;" : "=r"(rank));
    const int t = threadIdx.x;
    const int g = t >> 3;
    const int s_ = t & 7;
    const int u = rank * 32 + g;

    uint64_t wp[3][8][2];
#pragma unroll
    for (int r = 0; r < 3; r++) {
        const float4* Wrow = (const float4*)(W_hh + (size_t)(r * 256 + u) * H);
#pragma unroll
        for (int j = 0; j < 8; j++) {
            int jj = (j + s_) & 7;
            float4 w4 = Wrow[s_ * 8 + jj];
            wp[r][j][0] = packf2(w4.x, w4.y);
            wp[r][j][1] = packf2(w4.z, w4.w);
        }
    }
    float bhr = 0.f, bhz = 0.f, bhn = 0.f;
    if (s_ == 0) {
        bhr = b_hh[u];
        bhz = b_hh[256 + u];
        bhn = b_hh[512 + u];
    }
    if (t < H) { hbuf[0][t] = 0.f; hbuf[1][t] = 0.f; }

    uint32_t bar0 = smem_to_u32(bars);
    if (t == 0) { MBARRIER_INIT(bar0, 1); MBARRIER_INIT(bar0 + 8, 1); }
    uint32_t hb = smem_to_u32(hbuf);
    uint32_t peer_h[CLUSTER_N], peer_b[CLUSTER_N];
#pragma unroll
    for (int d = 0; d < CLUSTER_N; d++) {
        asm("mapa.shared::cluster.u32 %0, %1, %2;"
            : "=r"(peer_h[d]) : "r"(hb), "r"(d));
        asm("mapa.shared::cluster.u32 %0, %1, %2;"
            : "=r"(peer_b[d]) : "r"(bar0), "r"(d));
    }
    // all mbarriers initialized + h zeroed before any st.async flies
    asm volatile("barrier.cluster.arrive.aligned;" ::: "memory");
    asm volatile("barrier.cluster.wait.aligned;" ::: "memory");

    float gr_n = 0.f, gz_n = 0.f, gn_n = 0.f;
    if (s_ == 0) {
        gr_n = __ldg(gi + u);
        gz_n = __ldg(gi + 256 + u);
        gn_n = __ldg(gi + 512 + u);
    }
    const uint64_t z64 = packf2(0.f, 0.f);
    for (int step = 0; step < SEQ; step++) {
        const int p = step & 1, wb = p ^ 1;
        // open this step's fill phase on bar[wb]
        if (t == 0) MBARRIER_EXPECT_TX(bar0 + 8 * wb, 32 * CLUSTER_N * 4);

        float grc = gr_n, gzc = gz_n, gnc = gn_n;
        if (s_ == 0 && step + 1 < SEQ) {
            const float* gp = gi + (size_t)(step + 1) * G3H;
            gr_n = __ldg(gp + u);
            gz_n = __ldg(gp + 256 + u);
            gn_n = __ldg(gp + 512 + u);
        }
        if (step > 0) {
            int par = (p == 1) ? ((step >> 1) & 1) : (((step >> 1) + 1) & 1);
            MBAR_WAIT_PARITY(bar0 + 8 * p, par);
        }

        uint64_t pr = z64, pz = z64, pn = z64;
        const float4* h4 = (const float4*)hbuf[p];
#pragma unroll
        for (int j = 0; j < 8; j++) {
            int jj = (j + s_) & 7;
            float4 hv = h4[s_ * 8 + jj];
            uint64_t h01 = packf2(hv.x, hv.y);
            uint64_t h23 = packf2(hv.z, hv.w);
            pr = ffma2(h01, wp[0][j][0], pr);
            pz = ffma2(h01, wp[1][j][0], pz);
            pn = ffma2(h01, wp[2][j][0], pn);
            pr = ffma2(h23, wp[0][j][1], pr);
            pz = ffma2(h23, wp[1][j][1], pz);
            pn = ffma2(h23, wp[2][j][1], pn);
        }
        float ar = hsum2(pr), az = hsum2(pz), an = hsum2(pn);
#pragma unroll
        for (int off = 4; off > 0; off >>= 1) {
            ar += __shfl_down_sync(0xffffffffu, ar, off);
            az += __shfl_down_sync(0xffffffffu, az, off);
            an += __shfl_down_sync(0xffffffffu, an, off);
        }
        if (s_ == 0) {
            float r = 1.f / (1.f + __expf(-(grc + ar + bhr)));
            float z = 1.f / (1.f + __expf(-(gzc + az + bhz)));
            float n = tanhf(gnc + r * (an + bhn));
            float hp = hbuf[p][u];
            float h2 = (1.f - z) * n + z * hp;
            uint32_t off = (uint32_t)((wb * H + u) * 4);
            uint32_t bits = __float_as_uint(h2);
#pragma unroll
            for (int d = 0; d < CLUSTER_N; d++) {
                ST_ASYNC_U32(peer_h[d] + off, bits, peer_b[d] + 8 * wb);
            }
        }
    }
    // consume the final phase (step SEQ-1 wrote bar[0])
    MBAR_WAIT_PARITY(bar0, ((SEQ >> 1) + 1) & 1);
    if (t < 32) hT[rank * 32 + t] = hbuf[0][rank * 32 + t];
    asm volatile("barrier.cluster.arrive.aligned;" ::: "memory");
    asm volatile("barrier.cluster.wait.aligned;" ::: "memory");
}

// ---------------- output copy ----------------
__global__ void write_out(const float* __restrict__ hT, float* __restrict__ out,
                          int n) {
    int i = blockIdx.x * 256 + threadIdx.x;
    if (i < n) out[i] = hT[i & (H - 1)];
}

// ---------------- host launcher ----------------
extern "C" void kernel_launch(void* const* d_in, const int* in_sizes, int n_in,
                              void* d_out, int out_size) {
    const int* tokens = (const int*)d_in[0];
    const float* emb = (const float*)d_in[1];
    const float* Wq = (const float*)d_in[2];
    const float* bq = (const float*)d_in[3];
    const float* Wk = (const float*)d_in[4];
    const float* bk = (const float*)d_in[5];
    const float* Wv = (const float*)d_in[6];
    const float* bv = (const float*)d_in[7];
    const float* Wo = (const float*)d_in[8];
    const float* bo = (const float*)d_in[9];
    const float* ln_g = (const float*)d_in[10];
    const float* ln_b = (const float*)d_in[11];
    const float* W_ih = (const float*)d_in[12];
    const float* W_hh = (const float*)d_in[13];
    const float* b_ih = (const float*)d_in[14];
    const float* b_hh = (const float*)d_in[15];

    void* p;
    float *px, *ps, *py0, *py, *pgi, *phT;
    __half *pqh, *pkh, *pvh, *pvth, *pprobs, *poch;
    __half *pwqt, *pwkt, *pwvt, *pwot, *pwih;
    cudaGetSymbolAddress(&p, g_x); px = (float*)p;
    cudaGetSymbolAddress(&p, g_qh); pqh = (__half*)p;
    cudaGetSymbolAddress(&p, g_kh); pkh = (__half*)p;
    cudaGetSymbolAddress(&p, g_vh); pvh = (__half*)p;
    cudaGetSymbolAddress(&p, g_vth); pvth = (__half*)p;
    cudaGetSymbolAddress(&p, g_scores); ps = (float*)p;
    cudaGetSymbolAddress(&p, g_probs); pprobs = (__half*)p;
    cudaGetSymbolAddress(&p, g_och); poch = (__half*)p;
    cudaGetSymbolAddress(&p, g_y0); py0 = (float*)p;
    cudaGetSymbolAddress(&p, g_y); py = (float*)p;
    cudaGetSymbolAddress(&p, g_gi); pgi = (float*)p;
    cudaGetSymbolAddress(&p, g_hT); phT = (float*)p;
    cudaGetSymbolAddress(&p, g_wqt); pwqt = (__half*)p;
    cudaGetSymbolAddress(&p, g_wkt); pwkt = (__half*)p;
    cudaGetSymbolAddress(&p, g_wvt); pwvt = (__half*)p;
    cudaGetSymbolAddress(&p, g_wot); pwot = (__half*)p;
    cudaGetSymbolAddress(&p, g_wih); pwih = (__half*)p;

    const long long SH = (long long)SEQ * H;
    const long long SS = (long long)SEQ * SEQ;
    const long long HH = (long long)H * H;
    const float inv_scale = 1.0f / 16.0f;  // 1/sqrt(256)

    // 1) embedding
    embed_kernel<<<SEQ, H>>>(tokens, emb, px);

    // 2) weight transposes/converts to fp16
    dim3 gtw(H / 32, H / 32, NHEADS);
    transpose_h<float><<<gtw, 256>>>(Wq, pwqt, H, H, HH, HH);
    transpose_h<float><<<gtw, 256>>>(Wk, pwkt, H, H, HH, HH);
    transpose_h<float><<<gtw, 256>>>(Wv, pwvt, H, H, HH, HH);
    dim3 gtwo(H / 32, NHEADS * H / 32, 1);
    transpose_h<float><<<gtwo, 256>>>(Wo, pwot, NHEADS * H, H, 0, 0);
    to_half<<<(G3H * H + 255) / 256, 256>>>(W_ih, pwih, G3H * H);

    // 3) per-head Q/K/V projections -> fp16 outputs
    dim3 gqkv(H / 128, SEQ / 128, NHEADS);
    hgemm_nt<false, true, true, true><<<gqkv, 256>>>(
        px, pwqt, bq, pqh, H, H, H, H, 0, HH, H, SH, 1.f);
    hgemm_nt<false, true, true, true><<<gqkv, 256>>>(
        px, pwkt, bk, pkh, H, H, H, H, 0, HH, H, SH, 1.f);
    hgemm_nt<false, true, true, true><<<gqkv, 256>>>(
        px, pwvt, bv, pvh, H, H, H, H, 0, HH, H, SH, 1.f);

    // 3b) V transpose (fp16)
    dim3 gtv(H / 32, SEQ / 32, NHEADS);
    transpose_h<__half><<<gtv, 256>>>(pvh, pvth, SEQ, H, SH, SH);

    // 4) scores = Q @ K^T / 16 (fp32 out for softmax precision)
    dim3 gsc(SEQ / 128, SEQ / 128, NHEADS);
    hgemm_nt<true, true, false, false><<<gsc, 256>>>(
        pqh, pkh, nullptr, ps, H, H, H, SEQ, SH, SH, 0, SS, inv_scale);

    // 5) softmax -> fp16 probs
    softmax_rows<<<NHEADS * SEQ, 256>>>(ps, pprobs);

    // 6) O = probs @ V -> fp16 concat [S, NH*H]
    dim3 gav(H / 128, SEQ / 128, NHEADS);
    hgemm_nt<true, true, true, false><<<gav, 256>>>(
        pprobs, pvth, nullptr, poch, SEQ, SEQ, SEQ, NHEADS * H,
        SS, (long long)H * SEQ, 0, (long long)H, 1.f);

    // 7) output projection -> fp32 y0
    dim3 gop(H / 128, SEQ / 128, 1);
    hgemm_nt<true, true, false, true><<<gop, 256>>>(
        poch, pwot, bo, py0, NHEADS * H, NHEADS * H, NHEADS * H, H,
        0, 0, 0, 0, 1.f);

    // 8) residual + LayerNorm
    add_ln<<<SEQ, H>>>(px, py0, ln_g, ln_b, py);

    // 9) GRU input gates -> fp32 gi
    dim3 ggi(G3H / 128, SEQ / 128, 1);
    hgemm_nt<false, true, false, true><<<ggi, 256>>>(
        py, pwih, b_ih, pgi, H, H, H, G3H, 0, 0, 0, 0, 1.f);

    // 10) sequential GRU across 8-CTA cluster (st.async sync)
    gru_kernel<<<CLUSTER_N, 256>>>(pgi, W_hh, b_hh, phT);

    // 11) output
    write_out<<<(out_size + 255) / 256, 256>>>(phT, (float*)d_out, out_size);
}